// round 17
// baseline (speedup 1.0000x reference)
#include <cuda_runtime.h>

#define Bn 4
#define Nn 8192
#define Cin 64
#define Sn 2048
#define NS 32
#define R2 0.64f
#define NWORK 144          // worker blocks (grid = 4 + NWORK = 148)
#define NCHUNK 256         // (Bn*Sn)/32 chunks of 32 queries

// Scratch (device globals — no allocation allowed)
__device__ float g_F1[Bn * Nn * 128];    // per-point W1[:,3:]@features, [b][j][o]
__device__ float g_xs[Bn * Nn], g_ys[Bn * Nn], g_zs[Bn * Nn];  // SoA coords (orig order)
__device__ float g_sx[Bn * Nn], g_sy[Bn * Nn], g_sz[Bn * Nn];  // Morton-sorted coords
__device__ int   g_sid[Bn * Nn];                               // sorted -> original index
__device__ float g_W2T[128 * 256];       // W2 transposed: [c][o]
__device__ int   g_prog[Bn];             // fps progress (centers published)

// ---------- packed f32x2 helpers ----------
__device__ __forceinline__ unsigned long long pk2(float a, float b) {
    unsigned long long u;
    asm("mov.b64 %0, {%1,%2};" : "=l"(u) : "f"(a), "f"(b));
    return u;
}
__device__ __forceinline__ void upk2(unsigned long long u, float& a, float& b) {
    asm("mov.b64 {%0,%1}, %2;" : "=f"(a), "=f"(b) : "l"(u));
}
__device__ __forceinline__ unsigned long long add2(unsigned long long a, unsigned long long b) {
    unsigned long long r; asm("add.rn.f32x2 %0, %1, %2;" : "=l"(r) : "l"(a), "l"(b)); return r;
}
__device__ __forceinline__ unsigned long long mul2(unsigned long long a, unsigned long long b) {
    unsigned long long r; asm("mul.rn.f32x2 %0, %1, %2;" : "=l"(r) : "l"(a), "l"(b)); return r;
}
__device__ __forceinline__ unsigned long long fma2(unsigned long long a, unsigned long long b,
                                                   unsigned long long c) {
    unsigned long long r; asm("fma.rn.f32x2 %0, %1, %2, %3;" : "=l"(r) : "l"(a), "l"(b), "l"(c)); return r;
}

// ---------------------------------------------------------------------------
// Prep: SoA transpose of xyz + W2 transpose + progress reset
// ---------------------------------------------------------------------------
__global__ __launch_bounds__(256)
void prep_kernel(const float* __restrict__ xyz, const float* __restrict__ w2)
{
    const int i = blockIdx.x * 256 + threadIdx.x;
    if (i < Bn) g_prog[i] = 0;
    if (i < Bn * Nn) {
        g_xs[i] = xyz[3 * i + 0];
        g_ys[i] = xyz[3 * i + 1];
        g_zs[i] = xyz[3 * i + 2];
    }
    if (i < 256 * 128) {
        const int o = i >> 7, c = i & 127;
        g_W2T[c * 256 + o] = w2[i];
    }
}

// ---------------------------------------------------------------------------
// Morton counting sort (perf-only permutation; results are exact regardless).
// ---------------------------------------------------------------------------
__device__ __forceinline__ int spread3(int v) {
    return (v & 1) | ((v & 2) << 2) | ((v & 4) << 4);
}

__global__ __launch_bounds__(1024, 1)
void fps_sort_kernel()
{
    const int b = blockIdx.x;
    const int base = b * Nn;
    const int t = threadIdx.x;

    __shared__ int h[512];
    __shared__ int off[512];

    if (t < 512) h[t] = 0;
    __syncthreads();

    float px[8], py[8], pz[8];
    int cell[8];
#pragma unroll
    for (int k = 0; k < 8; k++) {
        const int j = base + k * 1024 + t;
        float x = g_xs[j], y = g_ys[j], z = g_zs[j];
        px[k] = x; py[k] = y; pz[k] = z;
        int bx = min(7, max(0, (int)((x + 16.f) * 0.25f)));
        int by = min(7, max(0, (int)((y + 16.f) * 0.25f)));
        int bz = min(7, max(0, (int)((z + 16.f) * 0.25f)));
        cell[k] = (spread3(bx) << 2) | (spread3(by) << 1) | spread3(bz);
        atomicAdd(&h[cell[k]], 1);
    }
    __syncthreads();

    int cnt = 0;
    if (t < 512) cnt = h[t];
    for (int d = 1; d < 512; d <<= 1) {
        int u = 0;
        if (t < 512 && t >= d) u = h[t - d];
        __syncthreads();
        if (t < 512) h[t] += u;
        __syncthreads();
    }
    if (t < 512) off[t] = h[t] - cnt;
    __syncthreads();

#pragma unroll
    for (int k = 0; k < 8; k++) {
        int pos = atomicAdd(&off[cell[k]], 1);
        g_sx[base + pos] = px[k];
        g_sy[base + pos] = py[k];
        g_sz[base + pos] = pz[k];
        g_sid[base + pos] = k * 1024 + t;
    }
}

// ---------------------------------------------------------------------------
// F1 precompute: F1[b][j][o] = sum_c W1[o][3+c] * features[b][c][j]
// ---------------------------------------------------------------------------
__global__ __launch_bounds__(256)
void f1_kernel(const float* __restrict__ features, const float* __restrict__ w1)
{
    const int b  = blockIdx.x >> 7;
    const int jt = blockIdx.x & 127;
    const int j0 = jt * 64;
    const int t  = threadIdx.x;
    const int o  = t & 127;
    const int jh = t >> 7;

    __shared__ float sf[64][64];
    for (int idx = t; idx < 64 * 64; idx += 256) {
        int c = idx >> 6, j = idx & 63;
        sf[c][j] = features[((size_t)b * Cin + c) * Nn + j0 + j];
    }
    float wr[64];
#pragma unroll
    for (int c = 0; c < 64; c++) wr[c] = w1[o * 67 + 3 + c];
    __syncthreads();

    for (int jg = 0; jg < 8; jg++) {
        const int jb = jh * 32 + jg * 4;
        float a0 = 0.f, a1 = 0.f, a2 = 0.f, a3 = 0.f;
#pragma unroll
        for (int c = 0; c < 64; c++) {
            float4 f = *(const float4*)&sf[c][jb];
            a0 += wr[c] * f.x; a1 += wr[c] * f.y;
            a2 += wr[c] * f.z; a3 += wr[c] * f.w;
        }
        const int j = j0 + jb;
        g_F1[((size_t)b * Nn + j + 0) * 128 + o] = a0;
        g_F1[((size_t)b * Nn + j + 1) * 128 + o] = a1;
        g_F1[((size_t)b * Nn + j + 2) * 128 + o] = a2;
        g_F1[((size_t)b * Nn + j + 3) * 128 + o] = a3;
    }
}

// ---------------------------------------------------------------------------
// Mega kernel v2: blocks 0-3 = R13-proven FPS (smem coord cache, zero global
// loads in the loop) + progress publish. Blocks 4..147 = workers (bq + MLP).
// ---------------------------------------------------------------------------
struct WorkerSmem {
    float H1[NS][128];     // 16 KB
    float pmax[1024];      // 4 KB
    int   sidx[32][32];    // 4 KB
    int   scnt[32];
    float rx[32], ry[32], rz[32];
};

extern __shared__ float dyn_smem[];   // 96 KB: fps coords OR worker scratch

__global__ __launch_bounds__(1024, 1)
void mega_kernel(float* __restrict__ new_xyz,
                 const float* __restrict__ w1, const float* __restrict__ b1,
                 const float* __restrict__ b2, float* __restrict__ pooled)
{
    const int t = threadIdx.x;
    const int lane = t & 31;
    const int w = t >> 5;

    if (blockIdx.x < Bn) {
        // ==================== FPS (R13 + progress publish) =================
        const int b = blockIdx.x;
        const int base = b * Nn;

        float* xc = dyn_smem;
        float* yc = dyn_smem + Nn;
        float* zc = dyn_smem + 2 * Nn;

#pragma unroll
        for (int k = 0; k < 8; k++) {
            const int j = k * 1024 + t;
            xc[j] = g_xs[base + j];
            yc[j] = g_ys[base + j];
            zc[j] = g_zs[base + j];
        }

        float dst[8];
        int gid[8];
        float x[8], y[8], z[8];
#pragma unroll
        for (int k = 0; k < 8; k++) {
            const int j = base + w * 256 + k * 32 + lane;
            x[k] = g_sx[j]; y[k] = g_sy[j]; z[k] = g_sz[j];
            gid[k] = g_sid[j];
            dst[k] = 1e10f;
        }

        float xmn = x[0], xmx = x[0], ymn = y[0], ymx = y[0], zmn = z[0], zmx = z[0];
#pragma unroll
        for (int k = 1; k < 8; k++) {
            xmn = fminf(xmn, x[k]); xmx = fmaxf(xmx, x[k]);
            ymn = fminf(ymn, y[k]); ymx = fmaxf(ymx, y[k]);
            zmn = fminf(zmn, z[k]); zmx = fmaxf(zmx, z[k]);
        }
#pragma unroll
        for (int o = 16; o > 0; o >>= 1) {
            xmn = fminf(xmn, __shfl_xor_sync(0xffffffffu, xmn, o));
            xmx = fmaxf(xmx, __shfl_xor_sync(0xffffffffu, xmx, o));
            ymn = fminf(ymn, __shfl_xor_sync(0xffffffffu, ymn, o));
            ymx = fmaxf(ymx, __shfl_xor_sync(0xffffffffu, ymx, o));
            zmn = fminf(zmn, __shfl_xor_sync(0xffffffffu, zmn, o));
            zmx = fmaxf(zmx, __shfl_xor_sync(0xffffffffu, zmx, o));
        }

        unsigned long long X2[4], Y2[4], Z2[4];
#pragma unroll
        for (int g = 0; g < 4; g++) {
            X2[g] = pk2(x[2 * g], x[2 * g + 1]);
            Y2[g] = pk2(y[2 * g], y[2 * g + 1]);
            Z2[g] = pk2(z[2 * g], z[2 * g + 1]);
        }

        __shared__ float sval[32];
        __shared__ int   sidx[32];
        __shared__ int   sgdx;

        float wmax = 1e10f;
        __syncthreads();   // coord cache ready
        float qx = xc[0], qy = yc[0], qz = zc[0];
        if (t == 0) {
            new_xyz[(b * Sn) * 3 + 0] = qx;
            new_xyz[(b * Sn) * 3 + 1] = qy;
            new_xyz[(b * Sn) * 3 + 2] = qz;
        }

        for (int i = 1; i < Sn; i++) {
            float dxl = fmaxf(0.f, fmaxf(xmn - qx, qx - xmx));
            float dyl = fmaxf(0.f, fmaxf(ymn - qy, qy - ymx));
            float dzl = fmaxf(0.f, fmaxf(zmn - qz, qz - zmx));
            float dbox = dxl * dxl + dyl * dyl + dzl * dzl;

            if (dbox < wmax) {
                const unsigned long long nqx = pk2(-qx, -qx);
                const unsigned long long nqy = pk2(-qy, -qy);
                const unsigned long long nqz = pk2(-qz, -qz);
#pragma unroll
                for (int g = 0; g < 4; g++) {
                    unsigned long long dx = add2(X2[g], nqx);
                    unsigned long long dy = add2(Y2[g], nqy);
                    unsigned long long dz = add2(Z2[g], nqz);
                    unsigned long long d  = fma2(dx, dx, fma2(dy, dy, mul2(dz, dz)));
                    float dlo, dhi; upk2(d, dlo, dhi);
                    dst[2 * g]     = fminf(dst[2 * g], dlo);
                    dst[2 * g + 1] = fminf(dst[2 * g + 1], dhi);
                }
                float m0 = fmaxf(dst[0], dst[1]), m1 = fmaxf(dst[2], dst[3]);
                float m2 = fmaxf(dst[4], dst[5]), m3 = fmaxf(dst[6], dst[7]);
                float vm = fmaxf(fmaxf(m0, m1), fmaxf(m2, m3));

                unsigned gmb = __reduce_max_sync(0xffffffffu, __float_as_uint(vm));
                float gmw = __uint_as_float(gmb);
                int cand = 0x7fffffff;
#pragma unroll
                for (int k = 0; k < 8; k++)
                    if (dst[k] == gmw) cand = min(cand, gid[k]);
                int widx = (int)__reduce_min_sync(0xffffffffu, (unsigned)cand);
                if (lane == 0) { sval[w] = gmw; sidx[w] = widx; }
                wmax = gmw;
            }
            __syncthreads();
            if (w == 0) {
                float v = sval[lane];
                int idv = sidx[lane];
                unsigned gmb = __reduce_max_sync(0xffffffffu, __float_as_uint(v));
                int cand = (__float_as_uint(v) == gmb) ? idv : 0x7fffffff;
                int gdx = (int)__reduce_min_sync(0xffffffffu, (unsigned)cand);
                if (lane == 0) {
                    sgdx = gdx;
                    new_xyz[(b * Sn + i) * 3 + 0] = xc[gdx];
                    new_xyz[(b * Sn + i) * 3 + 1] = yc[gdx];
                    new_xyz[(b * Sn + i) * 3 + 2] = zc[gdx];
                    if ((i & 31) == 31) {
                        int pv = i + 1;
                        asm volatile("st.release.gpu.b32 [%0], %1;"
                                     :: "l"(g_prog + b), "r"(pv) : "memory");
                    }
                }
            }
            __syncthreads();
            const int gq = sgdx;
            qx = xc[gq]; qy = yc[gq]; qz = zc[gq];
        }
        return;
    }

    // ===================== WORKER: bq + MLP per 32-query chunk =============
    WorkerSmem* sm = (WorkerSmem*)dyn_smem;
    const int wb = blockIdx.x - Bn;

    // chunk list (at most 2), ordered by within-batch position
    int c0 = wb, c1 = wb + NWORK, nch = 1;
    int order0 = c0, order1 = -1;
    if (c1 < NCHUNK) {
        nch = 2;
        if ((c1 & 63) < (c0 & 63)) { order0 = c1; order1 = c0; }
        else                       { order1 = c1; }
    }

    // per-thread hoisted stage constants
    const int o1  = t & 127;             // stage-1 output channel
    const float w1x = w1[o1 * 67 + 0];
    const float w1y = w1[o1 * 67 + 1];
    const float w1z = w1[o1 * 67 + 2];
    const float bb1 = b1[o1];
    const int o2  = t & 255;             // stage-2 output channel
    const int sg  = t >> 8;              // sample group 0..3
    const float bb2 = b2[o2];

    for (int ci = 0; ci < nch; ci++) {
        const int c  = (ci == 0) ? order0 : order1;
        const int b  = c >> 6;
        const int s0 = (c & 63) << 5;
        const int base = b * Nn;

        // wait for fps to publish centers [0, s0+32)
        if (t == 0) {
            const int need = s0 + 32;
            int p;
            do {
                asm volatile("ld.acquire.gpu.b32 %0, [%1];"
                             : "=r"(p) : "l"(g_prog + b) : "memory");
                if (p < need) __nanosleep(256);
            } while (p < need);
        }
        __syncthreads();

        // ---- ball query: warp w handles query s0 + w ----
        {
            const int gq = b * Sn + s0 + w;
            const float qx = __ldcg(&new_xyz[gq * 3 + 0]);
            const float qy = __ldcg(&new_xyz[gq * 3 + 1]);
            const float qz = __ldcg(&new_xyz[gq * 3 + 2]);

            int cnt = 0;
            int myidx = 0;
            for (int bs = 0; bs < Nn; bs += 32) {
                const int j = base + bs + lane;
                float dx = g_xs[j] - qx;
                float dy = g_ys[j] - qy;
                float dz = g_zs[j] - qz;
                float d2 = dx * dx + dy * dy + dz * dz;
                unsigned m = __ballot_sync(0xffffffffu, d2 < R2);
                while (m && cnt < NS) {
                    int l = __ffs(m) - 1;
                    m &= m - 1;
                    if (lane == cnt) myidx = bs + l;
                    cnt++;
                }
                if (cnt >= NS) break;
            }
            int first = __shfl_sync(0xffffffffu, myidx, 0);
            if (lane >= cnt) myidx = (cnt > 0) ? first : 0;
            sm->sidx[w][lane] = myidx;
            if (lane == 0) sm->scnt[w] = cnt;
        }
        __syncthreads();

        // ---- MLP: one query at a time with the whole block ----
        for (int qq = 0; qq < 32; qq++) {
            const int s  = s0 + qq;
            const int gq = b * Sn + s;
            const int cnt = sm->scnt[qq];

            if (t < 32) {
                const int id = sm->sidx[qq][t];
                sm->rx[t] = g_xs[base + id] - __ldcg(&new_xyz[gq * 3 + 0]);
                sm->ry[t] = g_ys[base + id] - __ldcg(&new_xyz[gq * 3 + 1]);
                sm->rz[t] = g_zs[base + id] - __ldcg(&new_xyz[gq * 3 + 2]);
            }
            __syncthreads();

            // stage 1: H1[n][o1], thread covers n = (t>>7) + 8k
#pragma unroll
            for (int k = 0; k < 4; k++) {
                const int n = (t >> 7) + 8 * k;
                float v;
                if (cnt > 0) {
                    const int id = sm->sidx[qq][n];
                    float f = g_F1[((size_t)(base + id)) * 128 + o1];
                    v = f + w1x * sm->rx[n] + w1y * sm->ry[n] + w1z * sm->rz[n] + bb1;
                } else {
                    v = bb1;
                }
                sm->H1[n][o1] = fmaxf(v, 0.f);
            }
            __syncthreads();

            // stage 2: thread (o2, sg) -> 8 samples
            float acc[8];
#pragma unroll
            for (int n = 0; n < 8; n++) acc[n] = 0.f;

            for (int cc = 0; cc < 128; cc += 16) {
                float wv[16];
#pragma unroll
                for (int i = 0; i < 16; i++)
                    wv[i] = __ldg(&g_W2T[(cc + i) * 256 + o2]);
#pragma unroll
                for (int n = 0; n < 8; n++) {
                    const float* h = &sm->H1[sg * 8 + n][cc];
                    float4 h0 = *(const float4*)(h);
                    float4 h1 = *(const float4*)(h + 4);
                    float4 h2 = *(const float4*)(h + 8);
                    float4 h3 = *(const float4*)(h + 12);
                    float a = acc[n];
                    a = fmaf(wv[0],  h0.x, a); a = fmaf(wv[1],  h0.y, a);
                    a = fmaf(wv[2],  h0.z, a); a = fmaf(wv[3],  h0.w, a);
                    a = fmaf(wv[4],  h1.x, a); a = fmaf(wv[5],  h1.y, a);
                    a = fmaf(wv[6],  h1.z, a); a = fmaf(wv[7],  h1.w, a);
                    a = fmaf(wv[8],  h2.x, a); a = fmaf(wv[9],  h2.y, a);
                    a = fmaf(wv[10], h2.z, a); a = fmaf(wv[11], h2.w, a);
                    a = fmaf(wv[12], h3.x, a); a = fmaf(wv[13], h3.y, a);
                    a = fmaf(wv[14], h3.z, a); a = fmaf(wv[15], h3.w, a);
                    acc[n] = a;
                }
            }

            float mx = 0.f;
#pragma unroll
            for (int n = 0; n < 8; n++)
                mx = fmaxf(mx, fmaxf(acc[n] + bb2, 0.f));
            sm->pmax[t] = mx;
            __syncthreads();

            if (t < 256) {
                float m = fmaxf(fmaxf(sm->pmax[t], sm->pmax[t + 256]),
                                fmaxf(sm->pmax[t + 512], sm->pmax[t + 768]));
                pooled[((size_t)b * 256 + t) * Sn + s] = m;
            }
            __syncthreads();
        }
    }
}

// ---------------------------------------------------------------------------
extern "C" void kernel_launch(void* const* d_in, const int* in_sizes, int n_in,
                              void* d_out, int out_size)
{
    const float* xyz      = (const float*)d_in[0];
    const float* features = (const float*)d_in[1];
    const float* w1       = (const float*)d_in[2];
    const float* b1       = (const float*)d_in[3];
    const float* w2       = (const float*)d_in[4];
    const float* b2       = (const float*)d_in[5];

    float* out     = (float*)d_out;
    float* new_xyz = out;
    float* pooled  = out + Bn * Sn * 3;

    const int smem_bytes = 3 * Nn * (int)sizeof(float);   // 96 KB
    static int attr_set = 0;
    if (!attr_set) {
        cudaFuncSetAttribute(mega_kernel,
                             cudaFuncAttributeMaxDynamicSharedMemorySize,
                             smem_bytes);
        attr_set = 1;
    }

    prep_kernel<<<128, 256>>>(xyz, w2);
    fps_sort_kernel<<<Bn, 1024>>>();
    f1_kernel<<<Bn * 128, 256>>>(features, w1);
    mega_kernel<<<Bn + NWORK, 1024, smem_bytes>>>(new_xyz, w1, b1, b2, pooled);
}